// round 14
// baseline (speedup 1.0000x reference)
#include <cuda_runtime.h>
#include <cuda_bf16.h>

#define B_ 128
#define L_ 196
#define F_ 2048
#define H_ 512
#define A_ 512
#define M_TOTAL (B_*L_)   // 25088

// ---------------- scratch (device globals; no cudaMalloc) ----------------
__device__ float g_dec[B_*A_];
__device__ float g_part[4*M_TOTAL];           // per-n-block partial scores
__device__ float g_alpha[B_*L_];
__device__ __nv_bfloat16 g_fh[(size_t)M_TOTAL*F_];   // features hi
__device__ __nv_bfloat16 g_fl[(size_t)M_TOTAL*F_];   // features lo
__device__ __nv_bfloat16 g_wh[(size_t)A_*F_];        // W_enc hi
__device__ __nv_bfloat16 g_wl[(size_t)A_*F_];        // W_enc lo

// ---------------- helpers ----------------
__device__ __forceinline__ unsigned smem_u32(const void* p) {
    unsigned a;
    asm("{ .reg .u64 t; cvta.to.shared.u64 t, %1; cvt.u32.u64 %0, t; }" : "=r"(a) : "l"(p));
    return a;
}

#define CP_ASYNC16(dst, src) \
    asm volatile("cp.async.cg.shared.global [%0], [%1], 16;" :: "r"(dst), "l"(src))
#define CP_COMMIT() asm volatile("cp.async.commit_group;" ::: "memory")
#define CP_WAIT(n)  asm volatile("cp.async.wait_group %0;" :: "n"(n) : "memory")

#define MMA_BF16(cc, aa, bb) \
    asm volatile("mma.sync.aligned.m16n8k16.row.col.f32.bf16.bf16.f32 " \
        "{%0,%1,%2,%3}, {%4,%5,%6,%7}, {%8,%9}, {%0,%1,%2,%3};" \
        : "+f"((cc)[0]), "+f"((cc)[1]), "+f"((cc)[2]), "+f"((cc)[3]) \
        : "r"((aa)[0]), "r"((aa)[1]), "r"((aa)[2]), "r"((aa)[3]), \
          "r"((bb)[0]), "r"((bb)[1]))

// ---------------------------------------------------------------------------
// Kernel 0: split fp32 -> (hi trunc bf16, lo bf16 of residual)
// ---------------------------------------------------------------------------
__global__ void split_kernel(const float* __restrict__ src,
                             __nv_bfloat16* __restrict__ hi,
                             __nv_bfloat16* __restrict__ lo, int n4) {
    int i = blockIdx.x * blockDim.x + threadIdx.x;
    if (i >= n4) return;
    float4 v = reinterpret_cast<const float4*>(src)[i];
    unsigned w0 = __float_as_uint(v.x), w1 = __float_as_uint(v.y);
    unsigned w2 = __float_as_uint(v.z), w3 = __float_as_uint(v.w);
    unsigned h01 = __byte_perm(w0, w1, 0x7632);
    unsigned h23 = __byte_perm(w2, w3, 0x7632);
    float l0 = v.x - __uint_as_float(w0 & 0xFFFF0000u);
    float l1 = v.y - __uint_as_float(w1 & 0xFFFF0000u);
    float l2 = v.z - __uint_as_float(w2 & 0xFFFF0000u);
    float l3 = v.w - __uint_as_float(w3 & 0xFFFF0000u);
    __nv_bfloat162 p01 = __float22bfloat162_rn(make_float2(l0, l1));
    __nv_bfloat162 p23 = __float22bfloat162_rn(make_float2(l2, l3));
    uint2 ho = make_uint2(h01, h23);
    uint2 lv = make_uint2(reinterpret_cast<unsigned&>(p01), reinterpret_cast<unsigned&>(p23));
    reinterpret_cast<uint2*>(hi)[i] = ho;
    reinterpret_cast<uint2*>(lo)[i] = lv;
}

// ---------------------------------------------------------------------------
// Kernel 1: dec[b,a] = hidden[b,:] . W_dec[a,:] + b_dec[a]
// ---------------------------------------------------------------------------
__global__ void dec_kernel(const float* __restrict__ hidden,
                           const float* __restrict__ W_dec,
                           const float* __restrict__ b_dec) {
    __shared__ float h[H_];
    int b = blockIdx.x;
    int tid = threadIdx.x;
    for (int i = tid; i < H_; i += blockDim.x) h[i] = hidden[b*H_ + i];
    __syncthreads();
    for (int a = tid; a < A_; a += blockDim.x) {
        const float4* w = reinterpret_cast<const float4*>(W_dec + (size_t)a*H_);
        float s = b_dec[a];
        #pragma unroll 8
        for (int k = 0; k < H_/4; k++) {
            float4 wv = w[k];
            const float* hp = &h[k*4];
            s += wv.x*hp[0] + wv.y*hp[1] + wv.z*hp[2] + wv.w*hp[3];
        }
        g_dec[b*A_ + a] = s;
    }
}

// ---------------------------------------------------------------------------
// Kernel 2: HMMA split-bf16 GEMM (128x128 tile) + fused relu/W_com partial
// K=32 chunks, 3-stage ring, 64B swizzled rows (R12 structure, proven).
// Grid (4, 196): the 4 n-block CTAs sharing an A tile launch adjacently so
// 3 of 4 A-tile reads hit L2 instead of DRAM.
// ---------------------------------------------------------------------------
#define TILE_BYTES  8192            // 128 rows * 64 B
#define STAGE_BYTES (4*TILE_BYTES)  // 32768
#define NSTAGE      3
#define NCHUNK      64              // K=2048 / 32

__global__ __launch_bounds__(256, 2)
void gemm_mma_kernel(const float* __restrict__ b_enc,
                     const float* __restrict__ W_com) {
    extern __shared__ char sm[];
    int tid = threadIdx.x;
    int l = tid & 31, w = tid >> 5;
    int wx = w & 3, wy = w >> 2;       // warp grid 2(m) x 4(n)
    int m0 = blockIdx.y * 128;
    int nb = blockIdx.x;

    const __nv_bfloat16* fh = g_fh;
    const __nv_bfloat16* fl = g_fl;
    const __nv_bfloat16* wh = g_wh;
    const __nv_bfloat16* wl = g_wl;

    float acc[4][4][4];
    #pragma unroll
    for (int mi = 0; mi < 4; mi++)
        #pragma unroll
        for (int ni = 0; ni < 4; ni++)
            #pragma unroll
            for (int j = 0; j < 4; j++) acc[mi][ni][j] = 0.f;

    unsigned sbase = smem_u32(sm);

    // cp.async slots: 512 quads per tile, 2 per thread per tile
    int row0 = tid >> 2, q0 = tid & 3;               // slot 0
    int row1 = (tid + 256) >> 2, q1 = tid & 3;       // slot 1 (rows 64..127)
    unsigned d0 = (unsigned)(row0*64 + ((q0 ^ ((row0>>1)&3))<<4));
    unsigned d1 = (unsigned)(row1*64 + ((q1 ^ ((row1>>1)&3))<<4));
    size_t gA0 = (size_t)(m0 + row0)*F_ + q0*8;
    size_t gA1 = (size_t)(m0 + row1)*F_ + q1*8;
    size_t gB0 = (size_t)(nb*128 + row0)*F_ + q0*8;
    size_t gB1 = (size_t)(nb*128 + row1)*F_ + q1*8;

    auto issue = [&](int kc, int s) {
        if (kc < NCHUNK) {
            unsigned st = sbase + s * STAGE_BYTES;
            size_t ka = (size_t)kc * 32;
            CP_ASYNC16(st + d0,                (const char*)(fh + gA0 + ka));
            CP_ASYNC16(st + d1,                (const char*)(fh + gA1 + ka));
            CP_ASYNC16(st + TILE_BYTES + d0,   (const char*)(fl + gA0 + ka));
            CP_ASYNC16(st + TILE_BYTES + d1,   (const char*)(fl + gA1 + ka));
            CP_ASYNC16(st + 2*TILE_BYTES + d0, (const char*)(wh + gB0 + ka));
            CP_ASYNC16(st + 2*TILE_BYTES + d1, (const char*)(wh + gB1 + ka));
            CP_ASYNC16(st + 3*TILE_BYTES + d0, (const char*)(wl + gB0 + ka));
            CP_ASYNC16(st + 3*TILE_BYTES + d1, (const char*)(wl + gB1 + ka));
        }
        CP_COMMIT();
    };

    issue(0, 0);
    issue(1, 1);

    int r0 = l >> 2;
    int fq = (l & 3) * 4;               // byte offset within a quad
    int cs = 0;        // consume stage for chunk c
    int is = 2;        // issue stage for chunk c+2

    for (int c = 0; c < NCHUNK; c++) {
        CP_WAIT(1);
        __syncthreads();
        issue(c + 2, is);
        is = (is + 1 == NSTAGE) ? 0 : is + 1;

        const char* base = sm + cs * STAGE_BYTES;
        cs = (cs + 1 == NSTAGE) ? 0 : cs + 1;
        const char* Ah = base;
        const char* Al = base + TILE_BYTES;
        const char* Bh = base + 2*TILE_BYTES;
        const char* Bl = base + 3*TILE_BYTES;

        #pragma unroll
        for (int kk = 0; kk < 2; kk++) {
            unsigned ah[4][4], alr[4][4], bh[4][2], bl[4][2];
            #pragma unroll
            for (int mi = 0; mi < 4; mi++) {
                int ra = wy*64 + mi*16 + r0;
                unsigned sw = (unsigned)((ra >> 1) & 3);
                unsigned o0 = (((2u*kk)   ^ sw) << 4);
                unsigned o1 = (((2u*kk+1) ^ sw) << 4);
                const char* p = Ah + ra*64 + fq;
                ah[mi][0] = *(const unsigned*)(p + o0);
                ah[mi][2] = *(const unsigned*)(p + o1);
                ah[mi][1] = *(const unsigned*)(p + 8*64 + o0);
                ah[mi][3] = *(const unsigned*)(p + 8*64 + o1);
            }
            #pragma unroll
            for (int ni = 0; ni < 4; ni++) {
                int rb = wx*32 + ni*8 + r0;
                unsigned sw = (unsigned)((rb >> 1) & 3);
                unsigned o0 = (((2u*kk)   ^ sw) << 4);
                unsigned o1 = (((2u*kk+1) ^ sw) << 4);
                const char* p = Bh + rb*64 + fq;
                bh[ni][0] = *(const unsigned*)(p + o0);
                bh[ni][1] = *(const unsigned*)(p + o1);
                const char* q2 = Bl + rb*64 + fq;
                bl[ni][0] = *(const unsigned*)(q2 + o0);
                bl[ni][1] = *(const unsigned*)(q2 + o1);
            }
            // Pass 1: all Ah*Bh
            #pragma unroll
            for (int mi = 0; mi < 4; mi++)
                #pragma unroll
                for (int ni = 0; ni < 4; ni++)
                    MMA_BF16(acc[mi][ni], ah[mi], bh[ni]);
            // Pass 2: all Ah*Bl
            #pragma unroll
            for (int mi = 0; mi < 4; mi++)
                #pragma unroll
                for (int ni = 0; ni < 4; ni++)
                    MMA_BF16(acc[mi][ni], ah[mi], bl[ni]);
            // Load Al fragments, then Pass 3: all Al*Bh
            #pragma unroll
            for (int mi = 0; mi < 4; mi++) {
                int ra = wy*64 + mi*16 + r0;
                unsigned sw = (unsigned)((ra >> 1) & 3);
                unsigned o0 = (((2u*kk)   ^ sw) << 4);
                unsigned o1 = (((2u*kk+1) ^ sw) << 4);
                const char* p = Al + ra*64 + fq;
                alr[mi][0] = *(const unsigned*)(p + o0);
                alr[mi][2] = *(const unsigned*)(p + o1);
                alr[mi][1] = *(const unsigned*)(p + 8*64 + o0);
                alr[mi][3] = *(const unsigned*)(p + 8*64 + o1);
            }
            #pragma unroll
            for (int mi = 0; mi < 4; mi++)
                #pragma unroll
                for (int ni = 0; ni < 4; ni++)
                    MMA_BF16(acc[mi][ni], alr[mi], bh[ni]);
        }
    }
    CP_WAIT(0);

    // ---- fused epilogue: relu(enc + b_enc + dec) * W_com, partial over 128 cols ----
    __syncthreads();
    float* red  = reinterpret_cast<float*>(sm);          // [128][4]
    float* val0 = reinterpret_cast<float*>(sm + 2048);   // [128]
    float* val1 = reinterpret_cast<float*>(sm + 2560);   // [128]
    float* wcm  = reinterpret_cast<float*>(sm + 3072);   // [128]
    int b0 = m0 / L_;
    int b1 = (m0 + 127) / L_;
    if (tid < 128) {
        int cg = nb*128 + tid;
        float be = b_enc[cg];
        val0[tid] = be + g_dec[b0*A_ + cg];
        val1[tid] = be + g_dec[b1*A_ + cg];
        wcm[tid]  = W_com[cg];
    }
    __syncthreads();

    int lim = (b0 + 1) * L_ - m0;   // local rows < lim belong to batch b0
    #pragma unroll
    for (int mi = 0; mi < 4; mi++) {
        int ra = wy*64 + mi*16 + r0;
        int rb = ra + 8;
        const float* va = (ra < lim) ? val0 : val1;
        const float* vb = (rb < lim) ? val0 : val1;
        float pa = 0.f, pb = 0.f;
        #pragma unroll
        for (int ni = 0; ni < 4; ni++) {
            int c0 = wx*32 + ni*8 + (l & 3)*2;
            int c1 = c0 + 1;
            pa += fmaxf(acc[mi][ni][0] + va[c0], 0.f) * wcm[c0]
                + fmaxf(acc[mi][ni][1] + va[c1], 0.f) * wcm[c1];
            pb += fmaxf(acc[mi][ni][2] + vb[c0], 0.f) * wcm[c0]
                + fmaxf(acc[mi][ni][3] + vb[c1], 0.f) * wcm[c1];
        }
        pa += __shfl_xor_sync(0xffffffffu, pa, 1);
        pa += __shfl_xor_sync(0xffffffffu, pa, 2);
        pb += __shfl_xor_sync(0xffffffffu, pb, 1);
        pb += __shfl_xor_sync(0xffffffffu, pb, 2);
        if ((l & 3) == 0) {
            red[ra*4 + wx] = pa;
            red[rb*4 + wx] = pb;
        }
    }
    __syncthreads();
    if (tid < 128) {
        float s = red[tid*4] + red[tid*4+1] + red[tid*4+2] + red[tid*4+3];
        g_part[nb*M_TOTAL + m0 + tid] = s;
    }
}

// ---------------------------------------------------------------------------
// Kernel 3: softmax over L per batch (sums 4 n-block partials + b_com)
// ---------------------------------------------------------------------------
__global__ void softmax_kernel(const float* __restrict__ b_com,
                               float* __restrict__ alpha_out) {
    __shared__ float red[8];
    int b = blockIdx.x;
    int tid = threadIdx.x;
    int lane = tid & 31, warp = tid >> 5;

    float v = -3.0e38f;
    if (tid < L_) {
        int idx = b*L_ + tid;
        v = g_part[idx] + g_part[M_TOTAL + idx]
          + g_part[2*M_TOTAL + idx] + g_part[3*M_TOTAL + idx] + b_com[0];
    }
    float m = v;
    #pragma unroll
    for (int off = 16; off; off >>= 1)
        m = fmaxf(m, __shfl_xor_sync(0xffffffffu, m, off));
    if (lane == 0) red[warp] = m;
    __syncthreads();
    if (tid == 0) {
        float t = red[0];
        #pragma unroll
        for (int i = 1; i < 8; i++) t = fmaxf(t, red[i]);
        red[0] = t;
    }
    __syncthreads();
    m = red[0];

    float e = (tid < L_) ? expf(v - m) : 0.f;
    float s = e;
    #pragma unroll
    for (int off = 16; off; off >>= 1)
        s += __shfl_xor_sync(0xffffffffu, s, off);
    __syncthreads();
    if (lane == 0) red[warp] = s;
    __syncthreads();
    if (tid == 0) {
        float t = 0.f;
        #pragma unroll
        for (int i = 0; i < 8; i++) t += red[i];
        red[0] = t;
    }
    __syncthreads();
    float inv = 1.f / red[0];
    if (tid < L_) alpha_out[b*L_ + tid] = e * inv;
}

// ---------------------------------------------------------------------------
// Kernel 4: weighted_features[b,f] = sum_l features[b,l,f] * alpha[b,l]
// float4 + two independent accumulator chains for MLP.
// grid (F/1024, B) = (2, 128), 256 threads, 4 floats/thread.
// ---------------------------------------------------------------------------
__global__ void weighted_kernel(const float* __restrict__ features,
                                const float* __restrict__ alpha,
                                float* __restrict__ out) {
    __shared__ float al[L_];
    int b  = blockIdx.y;
    int f  = blockIdx.x * 1024 + threadIdx.x * 4;
    int tid = threadIdx.x;
    for (int i = tid; i < L_; i += 256) al[i] = alpha[b*L_ + i];
    __syncthreads();

    float4 acc0 = make_float4(0.f, 0.f, 0.f, 0.f);
    float4 acc1 = make_float4(0.f, 0.f, 0.f, 0.f);
    const float* base = features + (size_t)b*L_*F_ + f;
    #pragma unroll 4
    for (int l = 0; l < L_/2; l++) {
        float4 v0 = *reinterpret_cast<const float4*>(base + (size_t)(2*l)*F_);
        float4 v1 = *reinterpret_cast<const float4*>(base + (size_t)(2*l+1)*F_);
        float a0 = al[2*l], a1 = al[2*l+1];
        acc0.x += v0.x * a0; acc0.y += v0.y * a0;
        acc0.z += v0.z * a0; acc0.w += v0.w * a0;
        acc1.x += v1.x * a1; acc1.y += v1.y * a1;
        acc1.z += v1.z * a1; acc1.w += v1.w * a1;
    }
    acc0.x += acc1.x; acc0.y += acc1.y; acc0.z += acc1.z; acc0.w += acc1.w;
    *reinterpret_cast<float4*>(out + (size_t)b*F_ + f) = acc0;
}

// ---------------------------------------------------------------------------
extern "C" void kernel_launch(void* const* d_in, const int* in_sizes, int n_in,
                              void* d_out, int out_size) {
    const float* features = (const float*)d_in[0];
    const float* hidden   = (const float*)d_in[1];
    const float* W_enc    = (const float*)d_in[2];
    const float* b_enc    = (const float*)d_in[3];
    const float* W_dec    = (const float*)d_in[4];
    const float* b_dec    = (const float*)d_in[5];
    const float* W_com    = (const float*)d_in[6];
    const float* b_com    = (const float*)d_in[7];
    float* out = (float*)d_out;

    float* wf_out = out;
    float* alpha_out;
    if (out_size >= B_*F_ + B_*L_) {
        alpha_out = out + (size_t)B_*F_;
    } else {
        float* dev_alpha;
        cudaGetSymbolAddress((void**)&dev_alpha, g_alpha);
        alpha_out = dev_alpha;
    }

    __nv_bfloat16 *fh, *fl, *wh, *wl;
    cudaGetSymbolAddress((void**)&fh, g_fh);
    cudaGetSymbolAddress((void**)&fl, g_fl);
    cudaGetSymbolAddress((void**)&wh, g_wh);
    cudaGetSymbolAddress((void**)&wl, g_wl);

    static bool attr_set = false;
    if (!attr_set) {
        cudaFuncSetAttribute(gemm_mma_kernel,
                             cudaFuncAttributeMaxDynamicSharedMemorySize, NSTAGE*STAGE_BYTES);
        attr_set = true;
    }

    // 0) split fp32 -> bf16 hi/lo
    int nf4 = M_TOTAL * F_ / 4;      // 12,845,056
    int nw4 = A_ * F_ / 4;           // 262,144
    split_kernel<<<(nf4 + 255)/256, 256>>>(features, fh, fl, nf4);
    split_kernel<<<(nw4 + 255)/256, 256>>>(W_enc, wh, wl, nw4);

    // 1) decoder context
    dec_kernel<<<B_, 256>>>(hidden, W_dec, b_dec);

    // 2) fused enc-GEMM + relu + W_com partial scores (tensor cores)
    //    grid (4, 196): n-blocks adjacent -> A tiles served from L2
    gemm_mma_kernel<<<dim3(4, M_TOTAL/128), 256, NSTAGE*STAGE_BYTES>>>(b_enc, W_com);

    // 3) softmax
    softmax_kernel<<<B_, 256>>>(b_com, alpha_out);

    // 4) weighted features
    weighted_kernel<<<dim3(F_/1024, B_), 256>>>(features, alpha_out, wf_out);
}

// round 15
// speedup vs baseline: 1.2927x; 1.2927x over previous
#include <cuda_runtime.h>
#include <cuda_fp16.h>

#define B_ 128
#define L_ 196
#define F_ 2048
#define H_ 512
#define A_ 512
#define M_TOTAL (B_*L_)   // 25088

// ---------------- scratch (device globals; no cudaMalloc) ----------------
__device__ float g_dec[B_*A_];
__device__ float g_part[4*M_TOTAL];           // per-n-block partial scores
__device__ float g_alpha[B_*L_];
__device__ __half g_fh[(size_t)M_TOTAL*F_];   // features hi (fp16 rn)
__device__ __half g_fl[(size_t)M_TOTAL*F_];   // features lo (fp16 rn of residual)
__device__ __half g_wh[(size_t)A_*F_];        // W_enc hi (fp16 rn)

// ---------------- helpers ----------------
__device__ __forceinline__ unsigned smem_u32(const void* p) {
    unsigned a;
    asm("{ .reg .u64 t; cvta.to.shared.u64 t, %1; cvt.u32.u64 %0, t; }" : "=r"(a) : "l"(p));
    return a;
}

#define CP_ASYNC16(dst, src) \
    asm volatile("cp.async.cg.shared.global [%0], [%1], 16;" :: "r"(dst), "l"(src))
#define CP_COMMIT() asm volatile("cp.async.commit_group;" ::: "memory")
#define CP_WAIT(n)  asm volatile("cp.async.wait_group %0;" :: "n"(n) : "memory")

#define MMA_F16(cc, aa, bb) \
    asm volatile("mma.sync.aligned.m16n8k16.row.col.f32.f16.f16.f32 " \
        "{%0,%1,%2,%3}, {%4,%5,%6,%7}, {%8,%9}, {%0,%1,%2,%3};" \
        : "+f"((cc)[0]), "+f"((cc)[1]), "+f"((cc)[2]), "+f"((cc)[3]) \
        : "r"((aa)[0]), "r"((aa)[1]), "r"((aa)[2]), "r"((aa)[3]), \
          "r"((bb)[0]), "r"((bb)[1]))

// ---------------------------------------------------------------------------
// Kernel 0a: split fp32 -> (hi fp16 rn, lo fp16 rn of residual)
// ---------------------------------------------------------------------------
__global__ void split_f16_kernel(const float* __restrict__ src,
                                 __half* __restrict__ hi,
                                 __half* __restrict__ lo, int n4) {
    int i = blockIdx.x * blockDim.x + threadIdx.x;
    if (i >= n4) return;
    float4 v = reinterpret_cast<const float4*>(src)[i];
    __half h0 = __float2half_rn(v.x);
    __half h1 = __float2half_rn(v.y);
    __half h2 = __float2half_rn(v.z);
    __half h3 = __float2half_rn(v.w);
    __half l0 = __float2half_rn(v.x - __half2float(h0));
    __half l1 = __float2half_rn(v.y - __half2float(h1));
    __half l2 = __float2half_rn(v.z - __half2float(h2));
    __half l3 = __float2half_rn(v.w - __half2float(h3));
    __half2 hp0 = __halves2half2(h0, h1), hp1 = __halves2half2(h2, h3);
    __half2 lp0 = __halves2half2(l0, l1), lp1 = __halves2half2(l2, l3);
    uint2 ho = make_uint2(reinterpret_cast<unsigned&>(hp0), reinterpret_cast<unsigned&>(hp1));
    uint2 lv = make_uint2(reinterpret_cast<unsigned&>(lp0), reinterpret_cast<unsigned&>(lp1));
    reinterpret_cast<uint2*>(hi)[i] = ho;
    reinterpret_cast<uint2*>(lo)[i] = lv;
}

// ---------------------------------------------------------------------------
// Kernel 0b: convert fp32 -> fp16 rn (hi only, for W_enc)
// ---------------------------------------------------------------------------
__global__ void cvt_f16_kernel(const float* __restrict__ src,
                               __half* __restrict__ hi, int n4) {
    int i = blockIdx.x * blockDim.x + threadIdx.x;
    if (i >= n4) return;
    float4 v = reinterpret_cast<const float4*>(src)[i];
    __half2 hp0 = __halves2half2(__float2half_rn(v.x), __float2half_rn(v.y));
    __half2 hp1 = __halves2half2(__float2half_rn(v.z), __float2half_rn(v.w));
    uint2 ho = make_uint2(reinterpret_cast<unsigned&>(hp0), reinterpret_cast<unsigned&>(hp1));
    reinterpret_cast<uint2*>(hi)[i] = ho;
}

// ---------------------------------------------------------------------------
// Kernel 1: dec[b,a] = hidden[b,:] . W_dec[a,:] + b_dec[a]
// ---------------------------------------------------------------------------
__global__ void dec_kernel(const float* __restrict__ hidden,
                           const float* __restrict__ W_dec,
                           const float* __restrict__ b_dec) {
    __shared__ float h[H_];
    int b = blockIdx.x;
    int tid = threadIdx.x;
    for (int i = tid; i < H_; i += blockDim.x) h[i] = hidden[b*H_ + i];
    __syncthreads();
    for (int a = tid; a < A_; a += blockDim.x) {
        const float4* w = reinterpret_cast<const float4*>(W_dec + (size_t)a*H_);
        float s = b_dec[a];
        #pragma unroll 8
        for (int k = 0; k < H_/4; k++) {
            float4 wv = w[k];
            const float* hp = &h[k*4];
            s += wv.x*hp[0] + wv.y*hp[1] + wv.z*hp[2] + wv.w*hp[3];
        }
        g_dec[b*A_ + a] = s;
    }
}

// ---------------------------------------------------------------------------
// Kernel 2: HMMA fp16 2-product GEMM (128x128 tile) + fused relu/W_com partial
// D = Ah*Bh + Al*Bh  (A = features split fp16 hi+lo, B = W_enc fp16 hi)
// K=32 chunks, 3-stage ring, 64B swizzled rows (proven R12 structure).
// Stage = 3 tiles * 8192 B = 24576 B; 3 stages = 73728 B -> 2 CTAs/SM.
// Grid (4, 196): n-block CTAs sharing an A tile adjacent -> A from L2.
// ---------------------------------------------------------------------------
#define TILE_BYTES  8192            // 128 rows * 64 B
#define STAGE_BYTES (3*TILE_BYTES)  // 24576
#define NSTAGE      3
#define NCHUNK      64              // K=2048 / 32

__global__ __launch_bounds__(256, 2)
void gemm_mma_kernel(const float* __restrict__ b_enc,
                     const float* __restrict__ W_com) {
    extern __shared__ char sm[];
    int tid = threadIdx.x;
    int l = tid & 31, w = tid >> 5;
    int wx = w & 3, wy = w >> 2;       // warp grid 2(m) x 4(n)
    int m0 = blockIdx.y * 128;
    int nb = blockIdx.x;

    const __half* fh = g_fh;
    const __half* fl = g_fl;
    const __half* wh = g_wh;

    float acc[4][4][4];
    #pragma unroll
    for (int mi = 0; mi < 4; mi++)
        #pragma unroll
        for (int ni = 0; ni < 4; ni++)
            #pragma unroll
            for (int j = 0; j < 4; j++) acc[mi][ni][j] = 0.f;

    unsigned sbase = smem_u32(sm);

    // cp.async slots: 512 quads per tile, 2 per thread per tile
    int row0 = tid >> 2, q0 = tid & 3;               // slot 0
    int row1 = (tid + 256) >> 2, q1 = tid & 3;       // slot 1 (rows 64..127)
    unsigned d0 = (unsigned)(row0*64 + ((q0 ^ ((row0>>1)&3))<<4));
    unsigned d1 = (unsigned)(row1*64 + ((q1 ^ ((row1>>1)&3))<<4));
    size_t gA0 = (size_t)(m0 + row0)*F_ + q0*8;
    size_t gA1 = (size_t)(m0 + row1)*F_ + q1*8;
    size_t gB0 = (size_t)(nb*128 + row0)*F_ + q0*8;
    size_t gB1 = (size_t)(nb*128 + row1)*F_ + q1*8;

    auto issue = [&](int kc, int s) {
        if (kc < NCHUNK) {
            unsigned st = sbase + s * STAGE_BYTES;
            size_t ka = (size_t)kc * 32;
            CP_ASYNC16(st + d0,                (const char*)(fh + gA0 + ka));
            CP_ASYNC16(st + d1,                (const char*)(fh + gA1 + ka));
            CP_ASYNC16(st + TILE_BYTES + d0,   (const char*)(fl + gA0 + ka));
            CP_ASYNC16(st + TILE_BYTES + d1,   (const char*)(fl + gA1 + ka));
            CP_ASYNC16(st + 2*TILE_BYTES + d0, (const char*)(wh + gB0 + ka));
            CP_ASYNC16(st + 2*TILE_BYTES + d1, (const char*)(wh + gB1 + ka));
        }
        CP_COMMIT();
    };

    issue(0, 0);
    issue(1, 1);

    int r0 = l >> 2;
    int fq = (l & 3) * 4;               // byte offset within a quad
    int cs = 0;        // consume stage for chunk c
    int is = 2;        // issue stage for chunk c+2

    for (int c = 0; c < NCHUNK; c++) {
        CP_WAIT(1);
        __syncthreads();
        issue(c + 2, is);
        is = (is + 1 == NSTAGE) ? 0 : is + 1;

        const char* base = sm + cs * STAGE_BYTES;
        cs = (cs + 1 == NSTAGE) ? 0 : cs + 1;
        const char* Ah = base;
        const char* Al = base + TILE_BYTES;
        const char* Bh = base + 2*TILE_BYTES;

        #pragma unroll
        for (int kk = 0; kk < 2; kk++) {
            unsigned ah[4][4], alr[4][4], bh[4][2];
            #pragma unroll
            for (int mi = 0; mi < 4; mi++) {
                int ra = wy*64 + mi*16 + r0;
                unsigned sw = (unsigned)((ra >> 1) & 3);
                unsigned o0 = (((2u*kk)   ^ sw) << 4);
                unsigned o1 = (((2u*kk+1) ^ sw) << 4);
                const char* p = Ah + ra*64 + fq;
                ah[mi][0] = *(const unsigned*)(p + o0);
                ah[mi][2] = *(const unsigned*)(p + o1);
                ah[mi][1] = *(const unsigned*)(p + 8*64 + o0);
                ah[mi][3] = *(const unsigned*)(p + 8*64 + o1);
            }
            #pragma unroll
            for (int ni = 0; ni < 4; ni++) {
                int rb = wx*32 + ni*8 + r0;
                unsigned sw = (unsigned)((rb >> 1) & 3);
                unsigned o0 = (((2u*kk)   ^ sw) << 4);
                unsigned o1 = (((2u*kk+1) ^ sw) << 4);
                const char* p = Bh + rb*64 + fq;
                bh[ni][0] = *(const unsigned*)(p + o0);
                bh[ni][1] = *(const unsigned*)(p + o1);
            }
            // Pass 1: all Ah*Bh
            #pragma unroll
            for (int mi = 0; mi < 4; mi++)
                #pragma unroll
                for (int ni = 0; ni < 4; ni++)
                    MMA_F16(acc[mi][ni], ah[mi], bh[ni]);
            // Load Al fragments, then Pass 2: all Al*Bh
            #pragma unroll
            for (int mi = 0; mi < 4; mi++) {
                int ra = wy*64 + mi*16 + r0;
                unsigned sw = (unsigned)((ra >> 1) & 3);
                unsigned o0 = (((2u*kk)   ^ sw) << 4);
                unsigned o1 = (((2u*kk+1) ^ sw) << 4);
                const char* p = Al + ra*64 + fq;
                alr[mi][0] = *(const unsigned*)(p + o0);
                alr[mi][2] = *(const unsigned*)(p + o1);
                alr[mi][1] = *(const unsigned*)(p + 8*64 + o0);
                alr[mi][3] = *(const unsigned*)(p + 8*64 + o1);
            }
            #pragma unroll
            for (int mi = 0; mi < 4; mi++)
                #pragma unroll
                for (int ni = 0; ni < 4; ni++)
                    MMA_F16(acc[mi][ni], alr[mi], bh[ni]);
        }
    }
    CP_WAIT(0);

    // ---- fused epilogue: relu(enc + b_enc + dec) * W_com, partial over 128 cols ----
    __syncthreads();
    float* red  = reinterpret_cast<float*>(sm);          // [128][4]
    float* val0 = reinterpret_cast<float*>(sm + 2048);   // [128]
    float* val1 = reinterpret_cast<float*>(sm + 2560);   // [128]
    float* wcm  = reinterpret_cast<float*>(sm + 3072);   // [128]
    int b0 = m0 / L_;
    int b1 = (m0 + 127) / L_;
    if (tid < 128) {
        int cg = nb*128 + tid;
        float be = b_enc[cg];
        val0[tid] = be + g_dec[b0*A_ + cg];
        val1[tid] = be + g_dec[b1*A_ + cg];
        wcm[tid]  = W_com[cg];
    }
    __syncthreads();

    int lim = (b0 + 1) * L_ - m0;   // local rows < lim belong to batch b0
    #pragma unroll
    for (int mi = 0; mi < 4; mi++) {
        int ra = wy*64 + mi*16 + r0;
        int rb = ra + 8;
        const float* va = (ra < lim) ? val0 : val1;
        const float* vb = (rb < lim) ? val0 : val1;
        float pa = 0.f, pb = 0.f;
        #pragma unroll
        for (int ni = 0; ni < 4; ni++) {
            int c0 = wx*32 + ni*8 + (l & 3)*2;
            int c1 = c0 + 1;
            pa += fmaxf(acc[mi][ni][0] + va[c0], 0.f) * wcm[c0]
                + fmaxf(acc[mi][ni][1] + va[c1], 0.f) * wcm[c1];
            pb += fmaxf(acc[mi][ni][2] + vb[c0], 0.f) * wcm[c0]
                + fmaxf(acc[mi][ni][3] + vb[c1], 0.f) * wcm[c1];
        }
        pa += __shfl_xor_sync(0xffffffffu, pa, 1);
        pa += __shfl_xor_sync(0xffffffffu, pa, 2);
        pb += __shfl_xor_sync(0xffffffffu, pb, 1);
        pb += __shfl_xor_sync(0xffffffffu, pb, 2);
        if ((l & 3) == 0) {
            red[ra*4 + wx] = pa;
            red[rb*4 + wx] = pb;
        }
    }
    __syncthreads();
    if (tid < 128) {
        float s = red[tid*4] + red[tid*4+1] + red[tid*4+2] + red[tid*4+3];
        g_part[nb*M_TOTAL + m0 + tid] = s;
    }
}

// ---------------------------------------------------------------------------
// Kernel 3: softmax over L per batch (sums 4 n-block partials + b_com)
// ---------------------------------------------------------------------------
__global__ void softmax_kernel(const float* __restrict__ b_com,
                               float* __restrict__ alpha_out) {
    __shared__ float red[8];
    int b = blockIdx.x;
    int tid = threadIdx.x;
    int lane = tid & 31, warp = tid >> 5;

    float v = -3.0e38f;
    if (tid < L_) {
        int idx = b*L_ + tid;
        v = g_part[idx] + g_part[M_TOTAL + idx]
          + g_part[2*M_TOTAL + idx] + g_part[3*M_TOTAL + idx] + b_com[0];
    }
    float m = v;
    #pragma unroll
    for (int off = 16; off; off >>= 1)
        m = fmaxf(m, __shfl_xor_sync(0xffffffffu, m, off));
    if (lane == 0) red[warp] = m;
    __syncthreads();
    if (tid == 0) {
        float t = red[0];
        #pragma unroll
        for (int i = 1; i < 8; i++) t = fmaxf(t, red[i]);
        red[0] = t;
    }
    __syncthreads();
    m = red[0];

    float e = (tid < L_) ? expf(v - m) : 0.f;
    float s = e;
    #pragma unroll
    for (int off = 16; off; off >>= 1)
        s += __shfl_xor_sync(0xffffffffu, s, off);
    __syncthreads();
    if (lane == 0) red[warp] = s;
    __syncthreads();
    if (tid == 0) {
        float t = 0.f;
        #pragma unroll
        for (int i = 0; i < 8; i++) t += red[i];
        red[0] = t;
    }
    __syncthreads();
    float inv = 1.f / red[0];
    if (tid < L_) alpha_out[b*L_ + tid] = e * inv;
}

// ---------------------------------------------------------------------------
// Kernel 4: weighted_features[b,f] = sum_l features[b,l,f] * alpha[b,l]
// grid (F/512, B), 256 threads, 2 floats/thread (best-known form)
// ---------------------------------------------------------------------------
__global__ void weighted_kernel(const float* __restrict__ features,
                                const float* __restrict__ alpha,
                                float* __restrict__ out) {
    __shared__ float al[L_];
    int b  = blockIdx.y;
    int f  = blockIdx.x * 512 + threadIdx.x * 2;
    int tid = threadIdx.x;
    for (int i = tid; i < L_; i += 256) al[i] = alpha[b*L_ + i];
    __syncthreads();

    float2 acc = make_float2(0.f, 0.f);
    const float* base = features + (size_t)b*L_*F_ + f;
    #pragma unroll 4
    for (int l = 0; l < L_; l++) {
        float2 v = *reinterpret_cast<const float2*>(base + (size_t)l*F_);
        float a = al[l];
        acc.x += v.x * a;
        acc.y += v.y * a;
    }
    *reinterpret_cast<float2*>(out + (size_t)b*F_ + f) = acc;
}

// ---------------------------------------------------------------------------
extern "C" void kernel_launch(void* const* d_in, const int* in_sizes, int n_in,
                              void* d_out, int out_size) {
    const float* features = (const float*)d_in[0];
    const float* hidden   = (const float*)d_in[1];
    const float* W_enc    = (const float*)d_in[2];
    const float* b_enc    = (const float*)d_in[3];
    const float* W_dec    = (const float*)d_in[4];
    const float* b_dec    = (const float*)d_in[5];
    const float* W_com    = (const float*)d_in[6];
    const float* b_com    = (const float*)d_in[7];
    float* out = (float*)d_out;

    float* wf_out = out;
    float* alpha_out;
    if (out_size >= B_*F_ + B_*L_) {
        alpha_out = out + (size_t)B_*F_;
    } else {
        float* dev_alpha;
        cudaGetSymbolAddress((void**)&dev_alpha, g_alpha);
        alpha_out = dev_alpha;
    }

    __half *fh, *fl, *wh;
    cudaGetSymbolAddress((void**)&fh, g_fh);
    cudaGetSymbolAddress((void**)&fl, g_fl);
    cudaGetSymbolAddress((void**)&wh, g_wh);

    static bool attr_set = false;
    if (!attr_set) {
        cudaFuncSetAttribute(gemm_mma_kernel,
                             cudaFuncAttributeMaxDynamicSharedMemorySize, NSTAGE*STAGE_BYTES);
        attr_set = true;
    }

    // 0) features -> fp16 hi/lo; W_enc -> fp16 hi
    int nf4 = M_TOTAL * F_ / 4;      // 12,845,056
    int nw4 = A_ * F_ / 4;           // 262,144
    split_f16_kernel<<<(nf4 + 255)/256, 256>>>(features, fh, fl, nf4);
    cvt_f16_kernel<<<(nw4 + 255)/256, 256>>>(W_enc, wh, nw4);

    // 1) decoder context
    dec_kernel<<<B_, 256>>>(hidden, W_dec, b_dec);

    // 2) fused enc-GEMM + relu + W_com partial scores (tensor cores, fp16 2-product)
    gemm_mma_kernel<<<dim3(4, M_TOTAL/128), 256, NSTAGE*STAGE_BYTES>>>(b_enc, W_com);

    // 3) softmax
    softmax_kernel<<<B_, 256>>>(b_com, alpha_out);

    // 4) weighted features
    weighted_kernel<<<dim3(F_/512, B_), 256>>>(features, alpha_out, wf_out);
}

// round 16
// speedup vs baseline: 1.9324x; 1.4949x over previous
#include <cuda_runtime.h>
#include <cuda_fp16.h>

#define B_ 128
#define L_ 196
#define F_ 2048
#define H_ 512
#define A_ 512
#define M_TOTAL (B_*L_)   // 25088

// ---------------- scratch (device globals; no cudaMalloc) ----------------
__device__ float g_dec[B_*A_];
__device__ float g_part[4*M_TOTAL];           // per-n-block partial scores
__device__ float g_alpha[B_*L_];
__device__ __half g_fh[(size_t)M_TOTAL*F_];   // features (fp16 rn)
__device__ __half g_wh[(size_t)A_*F_];        // W_enc (fp16 rn)

// ---------------- helpers ----------------
__device__ __forceinline__ unsigned smem_u32(const void* p) {
    unsigned a;
    asm("{ .reg .u64 t; cvta.to.shared.u64 t, %1; cvt.u32.u64 %0, t; }" : "=r"(a) : "l"(p));
    return a;
}

#define CP_ASYNC16(dst, src) \
    asm volatile("cp.async.cg.shared.global [%0], [%1], 16;" :: "r"(dst), "l"(src))
#define CP_COMMIT() asm volatile("cp.async.commit_group;" ::: "memory")
#define CP_WAIT(n)  asm volatile("cp.async.wait_group %0;" :: "n"(n) : "memory")

#define MMA_F16(cc, aa, bb) \
    asm volatile("mma.sync.aligned.m16n8k16.row.col.f32.f16.f16.f32 " \
        "{%0,%1,%2,%3}, {%4,%5,%6,%7}, {%8,%9}, {%0,%1,%2,%3};" \
        : "+f"((cc)[0]), "+f"((cc)[1]), "+f"((cc)[2]), "+f"((cc)[3]) \
        : "r"((aa)[0]), "r"((aa)[1]), "r"((aa)[2]), "r"((aa)[3]), \
          "r"((bb)[0]), "r"((bb)[1]))

// ---------------------------------------------------------------------------
// Kernel 0: convert fp32 -> fp16 rn
// ---------------------------------------------------------------------------
__global__ void cvt_f16_kernel(const float* __restrict__ src,
                               __half* __restrict__ dst, int n4) {
    int i = blockIdx.x * blockDim.x + threadIdx.x;
    if (i >= n4) return;
    float4 v = reinterpret_cast<const float4*>(src)[i];
    __half2 hp0 = __halves2half2(__float2half_rn(v.x), __float2half_rn(v.y));
    __half2 hp1 = __halves2half2(__float2half_rn(v.z), __float2half_rn(v.w));
    uint2 ho = make_uint2(reinterpret_cast<unsigned&>(hp0), reinterpret_cast<unsigned&>(hp1));
    reinterpret_cast<uint2*>(dst)[i] = ho;
}

// ---------------------------------------------------------------------------
// Kernel 1: dec[b,a] = hidden[b,:] . W_dec[a,:] + b_dec[a]
// ---------------------------------------------------------------------------
__global__ void dec_kernel(const float* __restrict__ hidden,
                           const float* __restrict__ W_dec,
                           const float* __restrict__ b_dec) {
    __shared__ float h[H_];
    int b = blockIdx.x;
    int tid = threadIdx.x;
    for (int i = tid; i < H_; i += blockDim.x) h[i] = hidden[b*H_ + i];
    __syncthreads();
    for (int a = tid; a < A_; a += blockDim.x) {
        const float4* w = reinterpret_cast<const float4*>(W_dec + (size_t)a*H_);
        float s = b_dec[a];
        #pragma unroll 8
        for (int k = 0; k < H_/4; k++) {
            float4 wv = w[k];
            const float* hp = &h[k*4];
            s += wv.x*hp[0] + wv.y*hp[1] + wv.z*hp[2] + wv.w*hp[3];
        }
        g_dec[b*A_ + a] = s;
    }
}

// ---------------------------------------------------------------------------
// Kernel 2: plain fp16 HMMA GEMM (128x128 tile) + fused relu/W_com partial
// D = A*B in fp16 inputs, fp32 accum.
// K=32 chunks, 3-stage ring, 64B swizzled rows (proven structure).
// Stage = 2 tiles * 8192 B = 16384 B; 3 stages = 49152 B -> 2 CTAs/SM.
// Grid (4, 196): n-block CTAs sharing an A tile adjacent -> A from L2.
// ---------------------------------------------------------------------------
#define TILE_BYTES  8192            // 128 rows * 64 B
#define STAGE_BYTES (2*TILE_BYTES)  // 16384
#define NSTAGE      3
#define NCHUNK      64              // K=2048 / 32

__global__ __launch_bounds__(256, 2)
void gemm_mma_kernel(const float* __restrict__ b_enc,
                     const float* __restrict__ W_com) {
    extern __shared__ char sm[];
    int tid = threadIdx.x;
    int l = tid & 31, w = tid >> 5;
    int wx = w & 3, wy = w >> 2;       // warp grid 2(m) x 4(n)
    int m0 = blockIdx.y * 128;
    int nb = blockIdx.x;

    const __half* fh = g_fh;
    const __half* wh = g_wh;

    float acc[4][4][4];
    #pragma unroll
    for (int mi = 0; mi < 4; mi++)
        #pragma unroll
        for (int ni = 0; ni < 4; ni++)
            #pragma unroll
            for (int j = 0; j < 4; j++) acc[mi][ni][j] = 0.f;

    unsigned sbase = smem_u32(sm);

    // cp.async slots: 512 quads per tile, 2 per thread per tile
    int row0 = tid >> 2, q0 = tid & 3;               // slot 0
    int row1 = (tid + 256) >> 2, q1 = tid & 3;       // slot 1 (rows 64..127)
    unsigned d0 = (unsigned)(row0*64 + ((q0 ^ ((row0>>1)&3))<<4));
    unsigned d1 = (unsigned)(row1*64 + ((q1 ^ ((row1>>1)&3))<<4));
    size_t gA0 = (size_t)(m0 + row0)*F_ + q0*8;
    size_t gA1 = (size_t)(m0 + row1)*F_ + q1*8;
    size_t gB0 = (size_t)(nb*128 + row0)*F_ + q0*8;
    size_t gB1 = (size_t)(nb*128 + row1)*F_ + q1*8;

    auto issue = [&](int kc, int s) {
        if (kc < NCHUNK) {
            unsigned st = sbase + s * STAGE_BYTES;
            size_t ka = (size_t)kc * 32;
            CP_ASYNC16(st + d0,              (const char*)(fh + gA0 + ka));
            CP_ASYNC16(st + d1,              (const char*)(fh + gA1 + ka));
            CP_ASYNC16(st + TILE_BYTES + d0, (const char*)(wh + gB0 + ka));
            CP_ASYNC16(st + TILE_BYTES + d1, (const char*)(wh + gB1 + ka));
        }
        CP_COMMIT();
    };

    issue(0, 0);
    issue(1, 1);

    int r0 = l >> 2;
    int fq = (l & 3) * 4;               // byte offset within a quad
    int cs = 0;        // consume stage for chunk c
    int is = 2;        // issue stage for chunk c+2

    for (int c = 0; c < NCHUNK; c++) {
        CP_WAIT(1);
        __syncthreads();
        issue(c + 2, is);
        is = (is + 1 == NSTAGE) ? 0 : is + 1;

        const char* base = sm + cs * STAGE_BYTES;
        cs = (cs + 1 == NSTAGE) ? 0 : cs + 1;
        const char* Ah = base;
        const char* Bh = base + TILE_BYTES;

        #pragma unroll
        for (int kk = 0; kk < 2; kk++) {
            unsigned ah[4][4], bh[4][2];
            #pragma unroll
            for (int mi = 0; mi < 4; mi++) {
                int ra = wy*64 + mi*16 + r0;
                unsigned sw = (unsigned)((ra >> 1) & 3);
                unsigned o0 = (((2u*kk)   ^ sw) << 4);
                unsigned o1 = (((2u*kk+1) ^ sw) << 4);
                const char* p = Ah + ra*64 + fq;
                ah[mi][0] = *(const unsigned*)(p + o0);
                ah[mi][2] = *(const unsigned*)(p + o1);
                ah[mi][1] = *(const unsigned*)(p + 8*64 + o0);
                ah[mi][3] = *(const unsigned*)(p + 8*64 + o1);
            }
            #pragma unroll
            for (int ni = 0; ni < 4; ni++) {
                int rb = wx*32 + ni*8 + r0;
                unsigned sw = (unsigned)((rb >> 1) & 3);
                unsigned o0 = (((2u*kk)   ^ sw) << 4);
                unsigned o1 = (((2u*kk+1) ^ sw) << 4);
                const char* p = Bh + rb*64 + fq;
                bh[ni][0] = *(const unsigned*)(p + o0);
                bh[ni][1] = *(const unsigned*)(p + o1);
            }
            #pragma unroll
            for (int mi = 0; mi < 4; mi++)
                #pragma unroll
                for (int ni = 0; ni < 4; ni++)
                    MMA_F16(acc[mi][ni], ah[mi], bh[ni]);
        }
    }
    CP_WAIT(0);

    // ---- fused epilogue: relu(enc + b_enc + dec) * W_com, partial over 128 cols ----
    __syncthreads();
    float* red  = reinterpret_cast<float*>(sm);          // [128][4]
    float* val0 = reinterpret_cast<float*>(sm + 2048);   // [128]
    float* val1 = reinterpret_cast<float*>(sm + 2560);   // [128]
    float* wcm  = reinterpret_cast<float*>(sm + 3072);   // [128]
    int b0 = m0 / L_;
    int b1 = (m0 + 127) / L_;
    if (tid < 128) {
        int cg = nb*128 + tid;
        float be = b_enc[cg];
        val0[tid] = be + g_dec[b0*A_ + cg];
        val1[tid] = be + g_dec[b1*A_ + cg];
        wcm[tid]  = W_com[cg];
    }
    __syncthreads();

    int lim = (b0 + 1) * L_ - m0;   // local rows < lim belong to batch b0
    #pragma unroll
    for (int mi = 0; mi < 4; mi++) {
        int ra = wy*64 + mi*16 + r0;
        int rb = ra + 8;
        const float* va = (ra < lim) ? val0 : val1;
        const float* vb = (rb < lim) ? val0 : val1;
        float pa = 0.f, pb = 0.f;
        #pragma unroll
        for (int ni = 0; ni < 4; ni++) {
            int c0 = wx*32 + ni*8 + (l & 3)*2;
            int c1 = c0 + 1;
            pa += fmaxf(acc[mi][ni][0] + va[c0], 0.f) * wcm[c0]
                + fmaxf(acc[mi][ni][1] + va[c1], 0.f) * wcm[c1];
            pb += fmaxf(acc[mi][ni][2] + vb[c0], 0.f) * wcm[c0]
                + fmaxf(acc[mi][ni][3] + vb[c1], 0.f) * wcm[c1];
        }
        pa += __shfl_xor_sync(0xffffffffu, pa, 1);
        pa += __shfl_xor_sync(0xffffffffu, pa, 2);
        pb += __shfl_xor_sync(0xffffffffu, pb, 1);
        pb += __shfl_xor_sync(0xffffffffu, pb, 2);
        if ((l & 3) == 0) {
            red[ra*4 + wx] = pa;
            red[rb*4 + wx] = pb;
        }
    }
    __syncthreads();
    if (tid < 128) {
        float s = red[tid*4] + red[tid*4+1] + red[tid*4+2] + red[tid*4+3];
        g_part[nb*M_TOTAL + m0 + tid] = s;
    }
}

// ---------------------------------------------------------------------------
// Kernel 3: softmax over L per batch (sums 4 n-block partials + b_com)
// ---------------------------------------------------------------------------
__global__ void softmax_kernel(const float* __restrict__ b_com,
                               float* __restrict__ alpha_out) {
    __shared__ float red[8];
    int b = blockIdx.x;
    int tid = threadIdx.x;
    int lane = tid & 31, warp = tid >> 5;

    float v = -3.0e38f;
    if (tid < L_) {
        int idx = b*L_ + tid;
        v = g_part[idx] + g_part[M_TOTAL + idx]
          + g_part[2*M_TOTAL + idx] + g_part[3*M_TOTAL + idx] + b_com[0];
    }
    float m = v;
    #pragma unroll
    for (int off = 16; off; off >>= 1)
        m = fmaxf(m, __shfl_xor_sync(0xffffffffu, m, off));
    if (lane == 0) red[warp] = m;
    __syncthreads();
    if (tid == 0) {
        float t = red[0];
        #pragma unroll
        for (int i = 1; i < 8; i++) t = fmaxf(t, red[i]);
        red[0] = t;
    }
    __syncthreads();
    m = red[0];

    float e = (tid < L_) ? expf(v - m) : 0.f;
    float s = e;
    #pragma unroll
    for (int off = 16; off; off >>= 1)
        s += __shfl_xor_sync(0xffffffffu, s, off);
    __syncthreads();
    if (lane == 0) red[warp] = s;
    __syncthreads();
    if (tid == 0) {
        float t = 0.f;
        #pragma unroll
        for (int i = 0; i < 8; i++) t += red[i];
        red[0] = t;
    }
    __syncthreads();
    float inv = 1.f / red[0];
    if (tid < L_) alpha_out[b*L_ + tid] = e * inv;
}

// ---------------------------------------------------------------------------
// Kernel 4: weighted_features[b,f] = sum_l fp16(features)[b,l,f] * alpha[b,l]
// reads g_fh (half) -> bytes halved. 4 halves per thread.
// grid (F/1024, B), 256 threads.
// ---------------------------------------------------------------------------
__global__ void weighted_kernel(const __half* __restrict__ fh,
                                const float* __restrict__ alpha,
                                float* __restrict__ out) {
    __shared__ float al[L_];
    int b  = blockIdx.y;
    int f  = blockIdx.x * 1024 + threadIdx.x * 4;
    int tid = threadIdx.x;
    for (int i = tid; i < L_; i += 256) al[i] = alpha[b*L_ + i];
    __syncthreads();

    float4 acc = make_float4(0.f, 0.f, 0.f, 0.f);
    const __half* base = fh + (size_t)b*L_*F_ + f;
    #pragma unroll 4
    for (int l = 0; l < L_; l++) {
        uint2 pv = *reinterpret_cast<const uint2*>(base + (size_t)l*F_);
        __half2 h01 = reinterpret_cast<__half2&>(pv.x);
        __half2 h23 = reinterpret_cast<__half2&>(pv.y);
        float2 v01 = __half22float2(h01);
        float2 v23 = __half22float2(h23);
        float a = al[l];
        acc.x += v01.x * a;
        acc.y += v01.y * a;
        acc.z += v23.x * a;
        acc.w += v23.y * a;
    }
    *reinterpret_cast<float4*>(out + (size_t)b*F_ + f) = acc;
}

// ---------------------------------------------------------------------------
extern "C" void kernel_launch(void* const* d_in, const int* in_sizes, int n_in,
                              void* d_out, int out_size) {
    const float* features = (const float*)d_in[0];
    const float* hidden   = (const float*)d_in[1];
    const float* W_enc    = (const float*)d_in[2];
    const float* b_enc    = (const float*)d_in[3];
    const float* W_dec    = (const float*)d_in[4];
    const float* b_dec    = (const float*)d_in[5];
    const float* W_com    = (const float*)d_in[6];
    const float* b_com    = (const float*)d_in[7];
    float* out = (float*)d_out;

    float* wf_out = out;
    float* alpha_out;
    if (out_size >= B_*F_ + B_*L_) {
        alpha_out = out + (size_t)B_*F_;
    } else {
        float* dev_alpha;
        cudaGetSymbolAddress((void**)&dev_alpha, g_alpha);
        alpha_out = dev_alpha;
    }

    __half *fh, *wh;
    cudaGetSymbolAddress((void**)&fh, g_fh);
    cudaGetSymbolAddress((void**)&wh, g_wh);

    static bool attr_set = false;
    if (!attr_set) {
        cudaFuncSetAttribute(gemm_mma_kernel,
                             cudaFuncAttributeMaxDynamicSharedMemorySize, NSTAGE*STAGE_BYTES);
        attr_set = true;
    }

    // 0) features, W_enc -> fp16
    int nf4 = M_TOTAL * F_ / 4;      // 12,845,056
    int nw4 = A_ * F_ / 4;           // 262,144
    cvt_f16_kernel<<<(nf4 + 255)/256, 256>>>(features, fh, nf4);
    cvt_f16_kernel<<<(nw4 + 255)/256, 256>>>(W_enc, wh, nw4);

    // 1) decoder context
    dec_kernel<<<B_, 256>>>(hidden, W_dec, b_dec);

    // 2) fused enc-GEMM + relu + W_com partial scores (plain fp16 tensor cores)
    gemm_mma_kernel<<<dim3(4, M_TOTAL/128), 256, NSTAGE*STAGE_BYTES>>>(b_enc, W_com);

    // 3) softmax
    softmax_kernel<<<B_, 256>>>(b_com, alpha_out);

    // 4) weighted features (reads fp16 copy)
    weighted_kernel<<<dim3(F_/1024, B_), 256>>>(fh, alpha_out, wf_out);
}